// round 1
// baseline (speedup 1.0000x reference)
#include <cuda_runtime.h>
#include <cuda_bf16.h>

// Dilate (zero-insertion upsample) with stride (2,2):
//   in : (16, 64, 256, 256) fp32
//   out: (16, 64, 512, 512) fp32, out[b,c,2i,2j] = in[b,c,i,j], rest 0.
//
// Pure memory-bound: 268 MB read + 1.074 GB write. One float4 (16B) of
// output per thread:
//   - odd output rows: store zero float4
//   - even output rows: load aligned float2 from input, store {x,0,y,0}
//
// All dims are powers of two -> shift/mask indexing only.

#ifndef DIL_THREADS
#define DIL_THREADS 256
#endif

__global__ void __launch_bounds__(DIL_THREADS)
Dilate_35708358099161_kernel(const float2* __restrict__ in2,
                             float4* __restrict__ out4)
{
    // total vec elements: 16*64*512*512/4 = 67,108,864  (grid sized exactly)
    unsigned int v = blockIdx.x * DIL_THREADS + threadIdx.x;

    // 512 floats per out row -> 128 float4 per row
    unsigned int c   = v & 127u;        // float4 index within out row
    unsigned int row = v >> 7;          // global out-row index = bc*512 + h
    unsigned int h   = row & 511u;      // out row within image

    if (h & 1u) {
        out4[v] = make_float4(0.f, 0.f, 0.f, 0.f);
    } else {
        unsigned int bc  = row >> 9;    // which (b,c) image, 0..1023
        unsigned int hin = h >> 1;      // input row, 0..255
        // input row = 256 floats = 128 float2; input float2 index = c
        float2 x = in2[(bc << 15) + (hin << 7) + c];  // bc*256*128 + hin*128 + c
        out4[v] = make_float4(x.x, 0.f, x.y, 0.f);
    }
}

extern "C" void kernel_launch(void* const* d_in, const int* in_sizes, int n_in,
                              void* d_out, int out_size)
{
    const float2* in2 = (const float2*)d_in[0];
    float4* out4 = (float4*)d_out;

    // out_size = 268,435,456 floats -> 67,108,864 float4
    const unsigned int nvec = (unsigned int)(out_size / 4);
    const unsigned int blocks = nvec / DIL_THREADS;  // exact: 262,144

    Dilate_35708358099161_kernel<<<blocks, DIL_THREADS>>>(in2, out4);
}